// round 2
// baseline (speedup 1.0000x reference)
#include <cuda_runtime.h>

// Problem constants
#define NB 32
#define NH 480
#define NW 640
#define HW (NH * NW)            // 307200 pixels per channel plane
#define PIX4 (HW / 4)           // 76800 float4 pixels per plane
#define THREADS 256
#define BLOCKS_PER_IMG (PIX4 / THREADS)   // 300
#define GRID (NB * BLOCKS_PER_IMG)        // 9600

__device__ float g_sum[NB];

__global__ void zero_sums_kernel() {
    if (threadIdx.x < NB) g_sum[threadIdx.x] = 0.0f;
}

__device__ __forceinline__ float clip01(float v) {
    return fminf(fmaxf(v, 0.0f), 1.0f);
}

// ---------------------------------------------------------------------------
// Pass 1: per-image sum of gray(clip(x * bf)) over all pixels.
// ---------------------------------------------------------------------------
__global__ void __launch_bounds__(THREADS)
reduce_mean_kernel(const float* __restrict__ x,
                   const float* __restrict__ brightness_f) {
    const int img = blockIdx.x / BLOCKS_PER_IMG;
    const int p4  = (blockIdx.x % BLOCKS_PER_IMG) * THREADS + threadIdx.x;

    const float4* base = (const float4*)(x + (size_t)img * 3 * HW);
    const float bf = brightness_f[img];

    float4 r4 = base[p4];
    float4 g4 = base[p4 + PIX4];
    float4 b4 = base[p4 + 2 * PIX4];

    float s = 0.0f;
    {
        float r = clip01(r4.x * bf), g = clip01(g4.x * bf), b = clip01(b4.x * bf);
        s += 0.299f * r + 0.587f * g + 0.114f * b;
        r = clip01(r4.y * bf); g = clip01(g4.y * bf); b = clip01(b4.y * bf);
        s += 0.299f * r + 0.587f * g + 0.114f * b;
        r = clip01(r4.z * bf); g = clip01(g4.z * bf); b = clip01(b4.z * bf);
        s += 0.299f * r + 0.587f * g + 0.114f * b;
        r = clip01(r4.w * bf); g = clip01(g4.w * bf); b = clip01(b4.w * bf);
        s += 0.299f * r + 0.587f * g + 0.114f * b;
    }

    // warp reduce
    #pragma unroll
    for (int off = 16; off > 0; off >>= 1)
        s += __shfl_down_sync(0xFFFFFFFFu, s, off);

    __shared__ float warp_sums[THREADS / 32];
    const int lane = threadIdx.x & 31;
    const int wid  = threadIdx.x >> 5;
    if (lane == 0) warp_sums[wid] = s;
    __syncthreads();

    if (wid == 0) {
        float v = (lane < THREADS / 32) ? warp_sums[lane] : 0.0f;
        #pragma unroll
        for (int off = 4; off > 0; off >>= 1)
            v += __shfl_down_sync(0xFFFFFFFFu, v, off);
        if (lane == 0) atomicAdd(&g_sum[img], v);
    }
}

// ---------------------------------------------------------------------------
// Hue adjust for one pixel — mirrors the jnp reference branch structure.
// ---------------------------------------------------------------------------
__device__ __forceinline__ void adjust_hue_px(float r, float g, float b, float hf,
                                              float& ro, float& go, float& bo) {
    float maxc = fmaxf(r, fmaxf(g, b));
    float minc = fminf(r, fminf(g, b));
    float v  = maxc;
    float cr = maxc - minc;
    float crd = (cr == 0.0f) ? 1.0f : cr;
    float s   = cr / ((maxc == 0.0f) ? 1.0f : maxc);
    float rc = (maxc - r) / crd;
    float gc = (maxc - g) / crd;
    float bc = (maxc - b) / crd;

    float h;
    if (maxc == r)      h = bc - gc;
    else if (maxc == g) h = 2.0f + rc - bc;
    else                h = 4.0f + gc - rc;

    h = h / 6.0f;
    h = h - floorf(h);       // mod 1
    h = h + hf;
    h = h - floorf(h);       // mod 1

    float i6 = h * 6.0f;
    float fi = floorf(i6);
    float f  = i6 - fi;
    int   i  = ((int)fi) % 6;

    float p = v * (1.0f - s);
    float q = v * (1.0f - f * s);
    float t = v * (1.0f - (1.0f - f) * s);

    switch (i) {
        case 0:  ro = v; go = t; bo = p; break;
        case 1:  ro = q; go = v; bo = p; break;
        case 2:  ro = p; go = v; bo = t; break;
        case 3:  ro = p; go = q; bo = v; break;
        case 4:  ro = t; go = p; bo = v; break;
        default: ro = v; go = p; bo = q; break;
    }
}

// ---------------------------------------------------------------------------
// Pass 2: full pipeline per pixel.
// ---------------------------------------------------------------------------
__global__ void __launch_bounds__(THREADS)
color_kernel(const float* __restrict__ x,
             const float* __restrict__ brightness_f,
             const float* __restrict__ contrast_f,
             const float* __restrict__ saturation_f,
             const float* __restrict__ hue_f,
             float* __restrict__ out) {
    const int img = blockIdx.x / BLOCKS_PER_IMG;
    const int p4  = (blockIdx.x % BLOCKS_PER_IMG) * THREADS + threadIdx.x;

    const size_t img_off = (size_t)img * 3 * HW;
    const float4* src = (const float4*)(x + img_off);
    float4* dst = (float4*)(out + img_off);

    const float bf = brightness_f[img];
    const float cf = contrast_f[img];
    const float sf = saturation_f[img];
    const float hf = hue_f[img];
    const float mean = g_sum[img] * (1.0f / (float)HW);

    float4 r4 = src[p4];
    float4 g4 = src[p4 + PIX4];
    float4 b4 = src[p4 + 2 * PIX4];

    float ro[4], go[4], bo[4];
    const float* rp = &r4.x;
    const float* gp = &g4.x;
    const float* bp = &b4.x;

    #pragma unroll
    for (int k = 0; k < 4; k++) {
        // brightness
        float r = clip01(rp[k] * bf);
        float g = clip01(gp[k] * bf);
        float b = clip01(bp[k] * bf);
        // contrast: blend with scalar mean
        r = clip01(cf * r + (1.0f - cf) * mean);
        g = clip01(cf * g + (1.0f - cf) * mean);
        b = clip01(cf * b + (1.0f - cf) * mean);
        // saturation: blend with per-pixel gray
        float gray = 0.299f * r + 0.587f * g + 0.114f * b;
        r = clip01(sf * r + (1.0f - sf) * gray);
        g = clip01(sf * g + (1.0f - sf) * gray);
        b = clip01(sf * b + (1.0f - sf) * gray);
        // hue
        adjust_hue_px(r, g, b, hf, ro[k], go[k], bo[k]);
    }

    dst[p4]            = make_float4(ro[0], ro[1], ro[2], ro[3]);
    dst[p4 + PIX4]     = make_float4(go[0], go[1], go[2], go[3]);
    dst[p4 + 2 * PIX4] = make_float4(bo[0], bo[1], bo[2], bo[3]);
}

extern "C" void kernel_launch(void* const* d_in, const int* in_sizes, int n_in,
                              void* d_out, int out_size) {
    const float* x  = (const float*)d_in[0];
    const float* bf = (const float*)d_in[1];
    const float* cf = (const float*)d_in[2];
    const float* sf = (const float*)d_in[3];
    const float* hf = (const float*)d_in[4];
    float* out = (float*)d_out;

    zero_sums_kernel<<<1, 32>>>();
    reduce_mean_kernel<<<GRID, THREADS>>>(x, bf);
    color_kernel<<<GRID, THREADS>>>(x, bf, cf, sf, hf, out);
}

// round 3
// speedup vs baseline: 1.0217x; 1.0217x over previous
#include <cuda_runtime.h>

// Problem constants
#define NB 32
#define NH 480
#define NW 640
#define HW (NH * NW)            // 307200 pixels per channel plane
#define PIX4 (HW / 4)           // 76800 float4 pixels per plane
#define THREADS 256
#define BLOCKS_PER_IMG (PIX4 / THREADS)   // 300
#define GRID (NB * BLOCKS_PER_IMG)        // 9600

// Per-block partial sums — every slot is written every launch, no init needed.
__device__ float g_partial[GRID];

__device__ __forceinline__ float clip01(float v) {
    return fminf(fmaxf(v, 0.0f), 1.0f);
}

// ---------------------------------------------------------------------------
// Pass 1: per-block partial sum of gray(clip(x * bf)).
// ---------------------------------------------------------------------------
__global__ void __launch_bounds__(THREADS)
reduce_mean_kernel(const float* __restrict__ x,
                   const float* __restrict__ brightness_f) {
    const int img = blockIdx.x / BLOCKS_PER_IMG;
    const int p4  = (blockIdx.x % BLOCKS_PER_IMG) * THREADS + threadIdx.x;

    const float4* base = (const float4*)(x + (size_t)img * 3 * HW);
    const float bf = brightness_f[img];

    float4 r4 = base[p4];
    float4 g4 = base[p4 + PIX4];
    float4 b4 = base[p4 + 2 * PIX4];

    float s = 0.0f;
    {
        float r = clip01(r4.x * bf), g = clip01(g4.x * bf), b = clip01(b4.x * bf);
        s += 0.299f * r + 0.587f * g + 0.114f * b;
        r = clip01(r4.y * bf); g = clip01(g4.y * bf); b = clip01(b4.y * bf);
        s += 0.299f * r + 0.587f * g + 0.114f * b;
        r = clip01(r4.z * bf); g = clip01(g4.z * bf); b = clip01(b4.z * bf);
        s += 0.299f * r + 0.587f * g + 0.114f * b;
        r = clip01(r4.w * bf); g = clip01(g4.w * bf); b = clip01(b4.w * bf);
        s += 0.299f * r + 0.587f * g + 0.114f * b;
    }

    // warp reduce
    #pragma unroll
    for (int off = 16; off > 0; off >>= 1)
        s += __shfl_down_sync(0xFFFFFFFFu, s, off);

    __shared__ float warp_sums[THREADS / 32];
    const int lane = threadIdx.x & 31;
    const int wid  = threadIdx.x >> 5;
    if (lane == 0) warp_sums[wid] = s;
    __syncthreads();

    if (wid == 0) {
        float v = (lane < THREADS / 32) ? warp_sums[lane] : 0.0f;
        #pragma unroll
        for (int off = 4; off > 0; off >>= 1)
            v += __shfl_down_sync(0xFFFFFFFFu, v, off);
        if (lane == 0) g_partial[blockIdx.x] = v;
    }
}

// ---------------------------------------------------------------------------
// Hue adjust for one pixel — mirrors the jnp reference branch structure.
// ---------------------------------------------------------------------------
__device__ __forceinline__ void adjust_hue_px(float r, float g, float b, float hf,
                                              float& ro, float& go, float& bo) {
    float maxc = fmaxf(r, fmaxf(g, b));
    float minc = fminf(r, fminf(g, b));
    float v  = maxc;
    float cr = maxc - minc;
    float crd = (cr == 0.0f) ? 1.0f : cr;
    float s   = cr / ((maxc == 0.0f) ? 1.0f : maxc);
    float rc = (maxc - r) / crd;
    float gc = (maxc - g) / crd;
    float bc = (maxc - b) / crd;

    float h;
    if (maxc == r)      h = bc - gc;
    else if (maxc == g) h = 2.0f + rc - bc;
    else                h = 4.0f + gc - rc;

    h = h / 6.0f;
    h = h - floorf(h);       // mod 1
    h = h + hf;
    h = h - floorf(h);       // mod 1

    float i6 = h * 6.0f;
    float fi = floorf(i6);
    float f  = i6 - fi;
    int   i  = ((int)fi) % 6;

    float p = v * (1.0f - s);
    float q = v * (1.0f - f * s);
    float t = v * (1.0f - (1.0f - f) * s);

    switch (i) {
        case 0:  ro = v; go = t; bo = p; break;
        case 1:  ro = q; go = v; bo = p; break;
        case 2:  ro = p; go = v; bo = t; break;
        case 3:  ro = p; go = q; bo = v; break;
        case 4:  ro = t; go = p; bo = v; break;
        default: ro = v; go = p; bo = q; break;
    }
}

// ---------------------------------------------------------------------------
// Pass 2: full pipeline per pixel. Blocks traverse in REVERSE order so the
// tail of x (most recently read by pass 1, hottest in L2) is consumed first.
// Output stores are streaming (evict-first) so they don't displace x in L2.
// ---------------------------------------------------------------------------
__global__ void __launch_bounds__(THREADS)
color_kernel(const float* __restrict__ x,
             const float* __restrict__ brightness_f,
             const float* __restrict__ contrast_f,
             const float* __restrict__ saturation_f,
             const float* __restrict__ hue_f,
             float* __restrict__ out) {
    const int rb  = GRID - 1 - blockIdx.x;           // reversed block id
    const int img = rb / BLOCKS_PER_IMG;
    const int p4  = (rb % BLOCKS_PER_IMG) * THREADS + threadIdx.x;

    const size_t img_off = (size_t)img * 3 * HW;
    const float4* src = (const float4*)(x + img_off);
    float4* dst = (float4*)(out + img_off);

    // ---- compute per-image mean from partials (all L2-hit) ----
    __shared__ float warp_sums[THREADS / 32];
    __shared__ float s_mean;
    {
        const float* part = g_partial + img * BLOCKS_PER_IMG;
        float v = 0.0f;
        for (int t = threadIdx.x; t < BLOCKS_PER_IMG; t += THREADS)
            v += part[t];
        #pragma unroll
        for (int off = 16; off > 0; off >>= 1)
            v += __shfl_down_sync(0xFFFFFFFFu, v, off);
        const int lane = threadIdx.x & 31;
        const int wid  = threadIdx.x >> 5;
        if (lane == 0) warp_sums[wid] = v;
        __syncthreads();
        if (threadIdx.x == 0) {
            float m = 0.0f;
            #pragma unroll
            for (int w = 0; w < THREADS / 32; w++) m += warp_sums[w];
            s_mean = m * (1.0f / (float)HW);
        }
        __syncthreads();
    }
    const float mean = s_mean;

    const float bf = brightness_f[img];
    const float cf = contrast_f[img];
    const float sf = saturation_f[img];
    const float hf = hue_f[img];

    float4 r4 = src[p4];
    float4 g4 = src[p4 + PIX4];
    float4 b4 = src[p4 + 2 * PIX4];

    float ro[4], go[4], bo[4];
    const float* rp = &r4.x;
    const float* gp = &g4.x;
    const float* bp = &b4.x;

    #pragma unroll
    for (int k = 0; k < 4; k++) {
        // brightness
        float r = clip01(rp[k] * bf);
        float g = clip01(gp[k] * bf);
        float b = clip01(bp[k] * bf);
        // contrast: blend with scalar mean
        r = clip01(cf * r + (1.0f - cf) * mean);
        g = clip01(cf * g + (1.0f - cf) * mean);
        b = clip01(cf * b + (1.0f - cf) * mean);
        // saturation: blend with per-pixel gray
        float gray = 0.299f * r + 0.587f * g + 0.114f * b;
        r = clip01(sf * r + (1.0f - sf) * gray);
        g = clip01(sf * g + (1.0f - sf) * gray);
        b = clip01(sf * b + (1.0f - sf) * gray);
        // hue
        adjust_hue_px(r, g, b, hf, ro[k], go[k], bo[k]);
    }

    // streaming stores: evict-first in L2, keep x resident
    __stcs(&dst[p4],            make_float4(ro[0], ro[1], ro[2], ro[3]));
    __stcs(&dst[p4 + PIX4],     make_float4(go[0], go[1], go[2], go[3]));
    __stcs(&dst[p4 + 2 * PIX4], make_float4(bo[0], bo[1], bo[2], bo[3]));
}

extern "C" void kernel_launch(void* const* d_in, const int* in_sizes, int n_in,
                              void* d_out, int out_size) {
    const float* x  = (const float*)d_in[0];
    const float* bf = (const float*)d_in[1];
    const float* cf = (const float*)d_in[2];
    const float* sf = (const float*)d_in[3];
    const float* hf = (const float*)d_in[4];
    float* out = (float*)d_out;

    reduce_mean_kernel<<<GRID, THREADS>>>(x, bf);
    color_kernel<<<GRID, THREADS>>>(x, bf, cf, sf, hf, out);
}

// round 4
// speedup vs baseline: 1.9320x; 1.8909x over previous
#include <cuda_runtime.h>

// Problem constants
#define NB 32
#define NH 480
#define NW 640
#define HW (NH * NW)            // 307200 pixels per channel plane
#define PIX4 (HW / 4)           // 76800 float4 pixels per plane
#define THREADS 256
#define BLOCKS_PER_IMG (PIX4 / THREADS)   // 300
#define GRID (NB * BLOCKS_PER_IMG)        // 9600

// Per-block partial sums — every slot is written every launch, no init needed.
__device__ float g_partial[GRID];

// ---------------------------------------------------------------------------
// Pass 1: per-block partial sum of gray(clip(x * bf)).
// ---------------------------------------------------------------------------
__global__ void __launch_bounds__(THREADS)
reduce_mean_kernel(const float* __restrict__ x,
                   const float* __restrict__ brightness_f) {
    const int img = blockIdx.x / BLOCKS_PER_IMG;
    const int p4  = (blockIdx.x % BLOCKS_PER_IMG) * THREADS + threadIdx.x;

    const float4* base = (const float4*)(x + (size_t)img * 3 * HW);
    const float bf = brightness_f[img];

    float4 r4 = base[p4];
    float4 g4 = base[p4 + PIX4];
    float4 b4 = base[p4 + 2 * PIX4];

    float s = 0.0f;
    {
        float r = __saturatef(r4.x * bf), g = __saturatef(g4.x * bf), b = __saturatef(b4.x * bf);
        s += fmaf(0.114f, b, fmaf(0.587f, g, 0.299f * r));
        r = __saturatef(r4.y * bf); g = __saturatef(g4.y * bf); b = __saturatef(b4.y * bf);
        s += fmaf(0.114f, b, fmaf(0.587f, g, 0.299f * r));
        r = __saturatef(r4.z * bf); g = __saturatef(g4.z * bf); b = __saturatef(b4.z * bf);
        s += fmaf(0.114f, b, fmaf(0.587f, g, 0.299f * r));
        r = __saturatef(r4.w * bf); g = __saturatef(g4.w * bf); b = __saturatef(b4.w * bf);
        s += fmaf(0.114f, b, fmaf(0.587f, g, 0.299f * r));
    }

    // warp reduce
    #pragma unroll
    for (int off = 16; off > 0; off >>= 1)
        s += __shfl_down_sync(0xFFFFFFFFu, s, off);

    __shared__ float warp_sums[THREADS / 32];
    const int lane = threadIdx.x & 31;
    const int wid  = threadIdx.x >> 5;
    if (lane == 0) warp_sums[wid] = s;
    __syncthreads();

    if (wid == 0) {
        float v = (lane < THREADS / 32) ? warp_sums[lane] : 0.0f;
        #pragma unroll
        for (int off = 4; off > 0; off >>= 1)
            v += __shfl_down_sync(0xFFFFFFFFu, v, off);
        if (lane == 0) g_partial[blockIdx.x] = v;
    }
}

// ---------------------------------------------------------------------------
// Pass 2: full pipeline per pixel, ALU-lean formulation.
//   - all clips folded into .SAT modifiers (fma pipe)
//   - hue via closed-form  out = v - chroma * saturate(min(k, 4-k)),
//     k = (n + 6h) mod 6, n = {5,3,1}  (algebraically identical to the
//     reference's sector/pqt selection; v*s == chroma exactly)
// ---------------------------------------------------------------------------
__global__ void __launch_bounds__(THREADS)
color_kernel(const float* __restrict__ x,
             const float* __restrict__ brightness_f,
             const float* __restrict__ contrast_f,
             const float* __restrict__ saturation_f,
             const float* __restrict__ hue_f,
             float* __restrict__ out) {
    const int rb  = GRID - 1 - blockIdx.x;           // reversed block id
    const int img = rb / BLOCKS_PER_IMG;
    const int p4  = (rb % BLOCKS_PER_IMG) * THREADS + threadIdx.x;

    const size_t img_off = (size_t)img * 3 * HW;
    const float4* src = (const float4*)(x + img_off);
    float4* dst = (float4*)(out + img_off);

    // ---- per-image mean from partials (all L2-hit) ----
    __shared__ float warp_sums[THREADS / 32];
    __shared__ float s_mean;
    {
        const float* part = g_partial + img * BLOCKS_PER_IMG;
        float v = 0.0f;
        for (int t = threadIdx.x; t < BLOCKS_PER_IMG; t += THREADS)
            v += part[t];
        #pragma unroll
        for (int off = 16; off > 0; off >>= 1)
            v += __shfl_down_sync(0xFFFFFFFFu, v, off);
        const int lane = threadIdx.x & 31;
        const int wid  = threadIdx.x >> 5;
        if (lane == 0) warp_sums[wid] = v;
        __syncthreads();
        if (threadIdx.x == 0) {
            float m = 0.0f;
            #pragma unroll
            for (int w = 0; w < THREADS / 32; w++) m += warp_sums[w];
            s_mean = m * (1.0f / (float)HW);
        }
        __syncthreads();
    }

    const float bf = brightness_f[img];
    const float cf = contrast_f[img];
    const float sf = saturation_f[img];
    const float hf = hue_f[img];
    const float cm   = (1.0f - cf) * s_mean;   // contrast blend constant
    const float omsf = 1.0f - sf;              // saturation blend coeff

    float4 r4 = src[p4];
    float4 g4 = src[p4 + PIX4];
    float4 b4 = src[p4 + 2 * PIX4];

    float ro[4], go[4], bo[4];
    const float* rp = &r4.x;
    const float* gp = &g4.x;
    const float* bp = &b4.x;

    #pragma unroll
    for (int k = 0; k < 4; k++) {
        // brightness (FMUL.SAT)
        float r = __saturatef(rp[k] * bf);
        float g = __saturatef(gp[k] * bf);
        float b = __saturatef(bp[k] * bf);
        // contrast blend with scalar mean (FFMA.SAT)
        r = __saturatef(fmaf(cf, r, cm));
        g = __saturatef(fmaf(cf, g, cm));
        b = __saturatef(fmaf(cf, b, cm));
        // saturation blend with per-pixel gray (FFMA.SAT)
        float gray = fmaf(0.114f, b, fmaf(0.587f, g, 0.299f * r));
        float sg = omsf * gray;
        r = __saturatef(fmaf(sf, r, sg));
        g = __saturatef(fmaf(sf, g, sg));
        b = __saturatef(fmaf(sf, b, sg));

        // ---- hue: closed form ----
        float maxc = fmaxf(r, fmaxf(g, b));
        float minc = fminf(r, fminf(g, b));
        float chroma = maxc - minc;
        float crd = (chroma == 0.0f) ? 1.0f : chroma;
        float rcp = __fdividef(1.0f, crd);

        float h;
        if (maxc == r)      h = (g - b) * rcp;
        else if (maxc == g) h = fmaf(b - r, rcp, 2.0f);
        else                h = fmaf(r - g, rcp, 4.0f);

        h = h * (1.0f / 6.0f);
        h = h - floorf(h);           // mod 1
        h = h + hf;
        h = h - floorf(h);           // mod 1
        float h6 = h * 6.0f;         // in [0, 6)

        float k5 = 5.0f + h6; if (k5 >= 6.0f) k5 -= 6.0f;
        float k3 = 3.0f + h6; if (k3 >= 6.0f) k3 -= 6.0f;
        float k1 = 1.0f + h6; if (k1 >= 6.0f) k1 -= 6.0f;

        ro[k] = fmaf(-chroma, __saturatef(fminf(k5, 4.0f - k5)), maxc);
        go[k] = fmaf(-chroma, __saturatef(fminf(k3, 4.0f - k3)), maxc);
        bo[k] = fmaf(-chroma, __saturatef(fminf(k1, 4.0f - k1)), maxc);
    }

    __stcs(&dst[p4],            make_float4(ro[0], ro[1], ro[2], ro[3]));
    __stcs(&dst[p4 + PIX4],     make_float4(go[0], go[1], go[2], go[3]));
    __stcs(&dst[p4 + 2 * PIX4], make_float4(bo[0], bo[1], bo[2], bo[3]));
}

extern "C" void kernel_launch(void* const* d_in, const int* in_sizes, int n_in,
                              void* d_out, int out_size) {
    const float* x  = (const float*)d_in[0];
    const float* bf = (const float*)d_in[1];
    const float* cf = (const float*)d_in[2];
    const float* sf = (const float*)d_in[3];
    const float* hf = (const float*)d_in[4];
    float* out = (float*)d_out;

    reduce_mean_kernel<<<GRID, THREADS>>>(x, bf);
    color_kernel<<<GRID, THREADS>>>(x, bf, cf, sf, hf, out);
}